// round 10
// baseline (speedup 1.0000x reference)
#include <cuda_runtime.h>
#include <cuda_fp16.h>
#include <math.h>
#include <stdint.h>

#define NN 8192
#define FF 256
#define LRA 0.2f
#define KSPLIT 2
#define MB 64                   // i-rows per block in k_attn
#define KT 32                   // j (K-dim) per tile
#define JSPAN (NN / KSPLIT)     // 4096
#define NTILE (JSPAN / KT)      // 128

#define PSTRIDE 40                       // halves per P row (80 B)
#define PBUF_BYTES (64 * PSTRIDE * 2)    // 5120
#define BSTRIDE 264                      // halves per B row (528 B)
#define BBUF_BYTES (32 * BSTRIDE * 2)    // 16896
#define ONESF 0x3C003C00u                // half2(1,1)

// ---------------- scratch (device globals: no allocs allowed) ----------------
__device__ __half g_Wh[NN * FF];            // 4 MB, fp16 Wh[j][f]
__device__ float g_s1[NN];
__device__ float g_s2[NN];
__device__ __half g_F1h[NN];                // exp(s2 - max)            (<=1)
__device__ __half g_F2h[NN];                // exp(.2(s2 - max))        (<=1)
__device__ __half g_s2h[NN];                // s2 in fp16 (for branch)
__device__ __half g_E1h[NN];                // exp(s1 + max - B)        (<=1)
__device__ __half g_E2h[NN];                // exp(.2(s1 + max) - B)    (<=1)
__device__ __half g_ms1h[NN];               // -s1 in fp16
__device__ float g_maxS2;
__device__ float g_Opart[KSPLIT * NN * FF]; // 16 MB partial numerators
__device__ float g_den[KSPLIT * NN];        // partial denominators

// ---------------- packed f32x2 helpers (for K1) ------------------------------
__device__ __forceinline__ unsigned long long pk_dup(float x) {
    unsigned long long r;
    asm("mov.b64 %0, {%1, %1};" : "=l"(r) : "f"(x));
    return r;
}
__device__ __forceinline__ void ffma2(unsigned long long &d,
                                      unsigned long long a,
                                      unsigned long long b) {
    asm("fma.rn.f32x2 %0, %1, %2, %0;" : "+l"(d) : "l"(a), "l"(b));
}

// ---------------- mma / ldmatrix / cp.async helpers --------------------------
__device__ __forceinline__ uint32_t smem_u32(const void* p) {
    uint32_t a;
    asm("{ .reg .u64 t; cvta.to.shared.u64 t, %1; cvt.u32.u64 %0, t; }"
        : "=r"(a) : "l"(p));
    return a;
}
__device__ __forceinline__ void cp16(uint32_t dst, const void* src) {
    asm volatile("cp.async.cg.shared.global [%0], [%1], 16;"
                 :: "r"(dst), "l"(src) : "memory");
}
#define LDM4(d, addr)                                                          \
    asm volatile("ldmatrix.sync.aligned.m8n8.x4.shared.b16 {%0,%1,%2,%3}, [%4];" \
        : "=r"((d)[0]), "=r"((d)[1]), "=r"((d)[2]), "=r"((d)[3]) : "r"(addr))
#define LDM4T(d0, d1, d2, d3, addr)                                            \
    asm volatile("ldmatrix.sync.aligned.m8n8.x4.trans.shared.b16 {%0,%1,%2,%3}, [%4];" \
        : "=r"(d0), "=r"(d1), "=r"(d2), "=r"(d3) : "r"(addr))

__device__ __forceinline__ void mma16816(float* c, const uint32_t* a,
                                         uint32_t b0, uint32_t b1) {
    asm volatile(
        "mma.sync.aligned.m16n8k16.row.col.f32.f16.f16.f32 "
        "{%0,%1,%2,%3}, {%4,%5,%6,%7}, {%8,%9}, {%0,%1,%2,%3};"
        : "+f"(c[0]), "+f"(c[1]), "+f"(c[2]), "+f"(c[3])
        : "r"(a[0]), "r"(a[1]), "r"(a[2]), "r"(a[3]), "r"(b0), "r"(b1));
}

// one half2 pair of attention weights from packed fp16 factors
__device__ __forceinline__ uint32_t wpair(uint32_t f1, uint32_t f2, uint32_t s2,
                                          uint32_t E1d, uint32_t E2d,
                                          uint32_t ms1d, int a0, int a1) {
    __half2 c1 = __hmul2(*(__half2*)&E1d, *(__half2*)&f1);
    __half2 c2 = __hmul2(*(__half2*)&E2d, *(__half2*)&f2);
    uint32_t mk;   // 0xFFFF per half-lane where s2 >= -s1
    asm("set.ge.u32.f16x2 %0, %1, %2;" : "=r"(mk) : "r"(s2), "r"(ms1d));
    uint32_t u1 = *(uint32_t*)&c1, u2 = *(uint32_t*)&c2;
    uint32_t am = (uint32_t)(a0 + (a1 << 16)) * 0xFFFFu;  // adj in {0,1}
    return ((u1 & mk) | (u2 & ~mk)) & am;
}

// ==================== K1: Wh = h @ W (fp16 out), fused s1/s2 =================
__global__ void __launch_bounds__(256, 1)
k_wh(const float* __restrict__ h, const float* __restrict__ W,
     const float* __restrict__ a) {
    __shared__ float As[64 * 32];
    __shared__ float Ws[32 * 256];
    const int tid = threadIdx.x;
    const int i0 = blockIdx.x * 64;
    const int ty = tid >> 5, tx = tid & 31;
    const int r0 = ty * 8, c0 = tx * 8;

    unsigned long long acc[8][4];
#pragma unroll
    for (int r = 0; r < 8; r++)
#pragma unroll
        for (int p = 0; p < 4; p++) acc[r][p] = 0ull;

    for (int ko = 0; ko < FF; ko += 32) {
        __syncthreads();
#pragma unroll
        for (int t = 0; t < 2; t++) {
            int idx = t * 256 + tid;
            int row = idx >> 3, c4 = idx & 7;
            float4 v = *(const float4*)&h[(size_t)(i0 + row) * FF + ko + c4 * 4];
            *(float4*)&As[row * 32 + c4 * 4] = v;
        }
#pragma unroll
        for (int t = 0; t < 8; t++) {
            int idx = t * 256 + tid;
            int row = idx >> 6, c4 = idx & 63;
            float4 v = *(const float4*)&W[(size_t)(ko + row) * FF + c4 * 4];
            *(float4*)&Ws[row * 256 + c4 * 4] = v;
        }
        __syncthreads();
        for (int kk = 0; kk < 32; kk += 4) {
            float4 pv[8];
#pragma unroll
            for (int r = 0; r < 8; r++)
                pv[r] = *(const float4*)&As[(r0 + r) * 32 + kk];
#pragma unroll
            for (int k4 = 0; k4 < 4; k4++) {
                ulonglong2 wa = *(const ulonglong2*)&Ws[(kk + k4) * 256 + c0];
                ulonglong2 wb = *(const ulonglong2*)&Ws[(kk + k4) * 256 + c0 + 4];
#pragma unroll
                for (int r = 0; r < 8; r++) {
                    float p = (k4 == 0) ? pv[r].x : (k4 == 1) ? pv[r].y
                             : (k4 == 2) ? pv[r].z : pv[r].w;
                    unsigned long long pd = pk_dup(p);
                    ffma2(acc[r][0], pd, wa.x);
                    ffma2(acc[r][1], pd, wa.y);
                    ffma2(acc[r][2], pd, wb.x);
                    ffma2(acc[r][3], pd, wb.y);
                }
            }
        }
    }
    float mat[8][8];
#pragma unroll
    for (int r = 0; r < 8; r++)
#pragma unroll
        for (int p = 0; p < 4; p++) {
            float2 f = *(float2*)&acc[r][p];
            mat[r][2 * p] = f.x; mat[r][2 * p + 1] = f.y;
        }
    float a1c[8], a2c[8];
#pragma unroll
    for (int c = 0; c < 8; c++) { a1c[c] = a[c0 + c]; a2c[c] = a[FF + c0 + c]; }
#pragma unroll
    for (int r = 0; r < 8; r++) {
        float p1 = 0.f, p2 = 0.f;
#pragma unroll
        for (int c = 0; c < 8; c++) { p1 += mat[r][c] * a1c[c]; p2 += mat[r][c] * a2c[c]; }
#pragma unroll
        for (int off = 16; off > 0; off >>= 1) {
            p1 += __shfl_down_sync(0xffffffffu, p1, off);
            p2 += __shfl_down_sync(0xffffffffu, p2, off);
        }
        if (tx == 0) { g_s1[i0 + r0 + r] = p1; g_s2[i0 + r0 + r] = p2; }
    }
#pragma unroll
    for (int r = 0; r < 8; r++) {
        __half2 q0 = __floats2half2_rn(mat[r][0], mat[r][1]);
        __half2 q1 = __floats2half2_rn(mat[r][2], mat[r][3]);
        __half2 q2 = __floats2half2_rn(mat[r][4], mat[r][5]);
        __half2 q3 = __floats2half2_rn(mat[r][6], mat[r][7]);
        uint4 u = make_uint4(*(uint32_t*)&q0, *(uint32_t*)&q1,
                             *(uint32_t*)&q2, *(uint32_t*)&q3);
        *(uint4*)&g_Wh[(size_t)(i0 + r0 + r) * FF + c0] = u;
    }
}

// ==================== K2: maxS2 = max(s2) ====================================
__global__ void k_max() {
    __shared__ float sm[256];
    int tid = threadIdx.x;
    float v = -1e30f;
    for (int i = tid; i < NN; i += 256) v = fmaxf(v, g_s2[i]);
    sm[tid] = v;
    __syncthreads();
    for (int s = 128; s > 0; s >>= 1) {
        if (tid < s) sm[tid] = fmaxf(sm[tid], sm[tid + s]);
        __syncthreads();
    }
    if (tid == 0) g_maxS2 = sm[0];
}

// ==================== K3: factorized-exp precompute (fp16 factors) ===========
// B_i = leakyrelu(s1_i + maxS2) >= max_j e_ij.  All stored factors are <= 1.
__global__ void k_factors() {
    int i = blockIdx.x * blockDim.x + threadIdx.x;
    if (i >= NN) return;
    float s1 = g_s1[i], s2 = g_s2[i], m = g_maxS2;
    float x = s1 + m;
    float B = x > 0.f ? x : LRA * x;
    g_F1h[i] = __float2half(__expf(s2 - m));
    g_F2h[i] = __float2half(__expf(LRA * (s2 - m)));
    g_s2h[i] = __float2half(s2);
    g_E1h[i] = __float2half(__expf(s1 + m - B));
    g_E2h[i] = __float2half(__expf(LRA * (s1 + m) - B));
    g_ms1h[i] = __float2half(-s1);
}

// ==================== K4: fp16 mma.sync fused masked-softmax @ Wh ============
// grid (KSPLIT, 128), 256 thr (8 warps, warp tile 32x64), 2 CTAs/SM.
// P x3, B x4 (cp.async dist-2), factors+adj prefetched to regs dist-1.
// Denominators accumulated by tensor core (ones-column MMA on warps 0-1).
__global__ void __launch_bounds__(256, 2)
k_attn(const int* __restrict__ adj) {
    extern __shared__ char smem[];
    const uint32_t PsB = smem_u32(smem);
    const uint32_t BsB = PsB + 3 * PBUF_BYTES;

    const int tid = threadIdx.x;
    const int lane = tid & 31, wid = tid >> 5;
    const int split = blockIdx.x;
    const int i0 = blockIdx.y * MB;
    const int jb = split * JSPAN;
    const int prow = tid >> 2;          // 0..63: this thread's P row
    const int jq = (tid & 3) * 8;       // 8 j's within tile
    const int wm = (wid & 1) * 32;      // warp M offset
    const int wn = (wid >> 1) * 64;     // warp N offset
    const bool doDen = (wid < 2);       // warps 0,1 accumulate denominators

    // per-row fp16 factors (duplicated into both half2 lanes)
    const uint32_t E1d = __half_as_ushort(g_E1h[i0 + prow]) * 0x10001u;
    const uint32_t E2d = __half_as_ushort(g_E2h[i0 + prow]) * 0x10001u;
    const uint32_t ms1d = __half_as_ushort(g_ms1h[i0 + prow]) * 0x10001u;

    const uint32_t Aoff = (uint32_t)(wm + (lane & 15)) * (PSTRIDE * 2) +
                          (uint32_t)(lane >> 4) * 16;
    const uint32_t Boff = (uint32_t)(lane & 15) * (BSTRIDE * 2) +
                          (uint32_t)(wn + (lane >> 4) * 8) * 2;
    const uint32_t Poff = (uint32_t)prow * (PSTRIDE * 2) + (uint32_t)jq * 2;

    float acc[2][8][4];
#pragma unroll
    for (int mf = 0; mf < 2; mf++)
#pragma unroll
        for (int nf = 0; nf < 8; nf++)
#pragma unroll
            for (int q = 0; q < 4; q++) acc[mf][nf][q] = 0.f;
    float dacc[2][4] = {{0.f, 0.f, 0.f, 0.f}, {0.f, 0.f, 0.f, 0.f}};

    // distance-1 register prefetch state (factors + adj for one future tile)
    uint4 f1q, f2q, s2q;
    int4 av0, av1;

    auto ldnext = [&](int tt) {
        const int j0 = jb + tt * KT + jq;
        f1q = *(const uint4*)&g_F1h[j0];
        f2q = *(const uint4*)&g_F2h[j0];
        s2q = *(const uint4*)&g_s2h[j0];
        const size_t base = (size_t)(i0 + prow) * NN + j0;
        av0 = *(const int4*)&adj[base];
        av1 = *(const int4*)&adj[base + 4];
    };
    auto buildP = [&](uint32_t pb) {   // consumes the prefetched registers
        uint32_t hp0 = wpair(f1q.x, f2q.x, s2q.x, E1d, E2d, ms1d, av0.x, av0.y);
        uint32_t hp1 = wpair(f1q.y, f2q.y, s2q.y, E1d, E2d, ms1d, av0.z, av0.w);
        uint32_t hp2 = wpair(f1q.z, f2q.z, s2q.z, E1d, E2d, ms1d, av1.x, av1.y);
        uint32_t hp3 = wpair(f1q.w, f2q.w, s2q.w, E1d, E2d, ms1d, av1.z, av1.w);
        asm volatile("st.shared.v4.b32 [%0], {%1,%2,%3,%4};"
                     :: "r"(pb + Poff), "r"(hp0), "r"(hp1), "r"(hp2), "r"(hp3)
                     : "memory");
    };
    auto cpB = [&](int tt, uint32_t bb) {
        const int j0 = jb + tt * KT;
#pragma unroll
        for (int k = 0; k < 4; k++) {
            int c = tid + k * 256;
            int jr = c >> 5, fo = (c & 31) * 8;
            cp16(bb + (uint32_t)jr * (BSTRIDE * 2) + (uint32_t)fo * 2,
                 &g_Wh[(size_t)(j0 + jr) * FF + fo]);
        }
    };

    // ---- prologue ----
    ldnext(0); buildP(PsB);
    cpB(0, BsB);
    asm volatile("cp.async.commit_group;" ::: "memory");
    ldnext(1); buildP(PsB + PBUF_BYTES);
    cpB(1, BsB + BBUF_BYTES);
    asm volatile("cp.async.commit_group;" ::: "memory");
    ldnext(2);                       // regs for buildP(2) in iteration 0
    cpB(2, BsB + 2 * BBUF_BYTES);
    asm volatile("cp.async.commit_group;" ::: "memory");
    asm volatile("cp.async.wait_group 2;" ::: "memory");
    __syncthreads();

    int p3 = 0, b4 = 0, p3n = 2, b4n = 3;
#pragma unroll 1
    for (int t = 0; t < NTILE; t++) {
        // ---- MMA(t) ----
        const uint32_t Pb = PsB + (uint32_t)p3 * PBUF_BYTES;
        const uint32_t Bb = BsB + (uint32_t)b4 * BBUF_BYTES;
#pragma unroll
        for (int kf = 0; kf < 2; kf++) {
            uint32_t afr0[4], afr1[4];
            LDM4(afr0, Pb + Aoff + kf * 32);
            LDM4(afr1, Pb + Aoff + 16 * (PSTRIDE * 2) + kf * 32);
#pragma unroll
            for (int nfp = 0; nfp < 4; nfp++) {
                uint32_t b0, b1, b2, b3;
                LDM4T(b0, b1, b2, b3, Bb + Boff + nfp * 32 + kf * 16 * (BSTRIDE * 2));
                mma16816(acc[0][2 * nfp],     afr0, b0, b1);
                mma16816(acc[1][2 * nfp],     afr1, b0, b1);
                mma16816(acc[0][2 * nfp + 1], afr0, b2, b3);
                mma16816(acc[1][2 * nfp + 1], afr1, b2, b3);
            }
            if (doDen) {    // row sums via ones-column MMA (exactly consistent)
                mma16816(dacc[0], afr0, ONESF, ONESF);
                mma16816(dacc[1], afr1, ONESF, ONESF);
            }
        }
        // ---- overlapped producer work (P regs were loaded last iteration) ----
        if (t + 2 < NTILE) buildP(PsB + (uint32_t)p3n * PBUF_BYTES);
        if (t + 3 < NTILE) {
            cpB(t + 3, BsB + (uint32_t)b4n * BBUF_BYTES);
            ldnext(t + 3);   // latency spans barrier + next MMA
        }
        asm volatile("cp.async.commit_group;" ::: "memory");
        asm volatile("cp.async.wait_group 2;" ::: "memory");
        __syncthreads();
        p3 = (p3 + 1 == 3) ? 0 : p3 + 1;
        p3n = (p3n + 1 == 3) ? 0 : p3n + 1;
        b4 = (b4 + 1) & 3;
        b4n = (b4n + 1) & 3;
    }

    // ---- denominators from tensor-core row sums ----
    const int gid = lane >> 2, tig = lane & 3;
    if (doDen && tig == 0) {
        g_den[split * NN + i0 + wm + gid]          = dacc[0][0];
        g_den[split * NN + i0 + wm + gid + 8]      = dacc[0][2];
        g_den[split * NN + i0 + wm + 16 + gid]     = dacc[1][0];
        g_den[split * NN + i0 + wm + 16 + gid + 8] = dacc[1][2];
    }

    // ---- partial O store ----
    float* Ob = g_Opart + (size_t)split * NN * FF;
#pragma unroll
    for (int mf = 0; mf < 2; mf++)
#pragma unroll
        for (int nf = 0; nf < 8; nf++) {
            int r = i0 + wm + mf * 16 + gid;
            int c = wn + nf * 8 + 2 * tig;
            *(float2*)&Ob[(size_t)r * FF + c] =
                make_float2(acc[mf][nf][0], acc[mf][nf][1]);
            *(float2*)&Ob[(size_t)(r + 8) * FF + c] =
                make_float2(acc[mf][nf][2], acc[mf][nf][3]);
        }
}

// ==================== K5: combine splits, divide, elu ========================
__global__ void k_final(float* __restrict__ out) {
    int idx = blockIdx.x * blockDim.x + threadIdx.x;   // float4 index
    int i = idx >> 6;                                   // row
    float den = g_den[i] + g_den[NN + i];
    float inv = 1.0f / den;
    const float4* O = (const float4*)g_Opart;
    const int STR = NN * FF / 4;
    float4 a = O[idx], b = O[idx + STR];
    float4 r;
    r.x = (a.x + b.x) * inv;
    r.y = (a.y + b.y) * inv;
    r.z = (a.z + b.z) * inv;
    r.w = (a.w + b.w) * inv;
    r.x = r.x > 0.f ? r.x : expm1f(r.x);
    r.y = r.y > 0.f ? r.y : expm1f(r.y);
    r.z = r.z > 0.f ? r.z : expm1f(r.z);
    r.w = r.w > 0.f ? r.w : expm1f(r.w);
    ((float4*)out)[idx] = r;
}

// ==================== launch =================================================
extern "C" void kernel_launch(void* const* d_in, const int* in_sizes, int n_in,
                              void* d_out, int out_size) {
    const float* h   = (const float*)d_in[0];
    const int*   adj = (const int*)d_in[1];
    const float* W   = (const float*)d_in[2];
    const float* a   = (const float*)d_in[3];
    float* out = (float*)d_out;

    k_wh<<<NN / 64, 256>>>(h, W, a);
    k_max<<<1, 256>>>();
    k_factors<<<NN / 256, 256>>>();

    const int smem_attn = 3 * PBUF_BYTES + 4 * BBUF_BYTES;   // 82944
    cudaFuncSetAttribute(k_attn, cudaFuncAttributeMaxDynamicSharedMemorySize,
                         smem_attn);
    k_attn<<<dim3(KSPLIT, NN / MB), 256, smem_attn>>>(adj);

    k_final<<<(NN * FF / 4) / 256, 256>>>(out);
}

// round 11
// speedup vs baseline: 1.4987x; 1.4987x over previous
#include <cuda_runtime.h>
#include <cuda_fp16.h>
#include <math.h>
#include <stdint.h>

#define NN 8192
#define FF 256
#define LRA 0.2f
#define KSPLIT 2
#define MB 64                   // i-rows per block in k_attn
#define KT 32                   // j (K-dim) per tile
#define JSPAN (NN / KSPLIT)     // 4096
#define NTILE (JSPAN / KT)      // 128

#define PSTRIDE 40                       // halves per P row (80 B)
#define PBUF_BYTES (64 * PSTRIDE * 2)    // 5120
#define BSTRIDE 264                      // halves per B row (528 B)
#define BBUF_BYTES (32 * BSTRIDE * 2)    // 16896
#define ONESF 0x3C003C00u                // half2(1,1)

// ---------------- scratch (device globals: no allocs allowed) ----------------
__device__ __half g_Wh[NN * FF];            // 4 MB, fp16 Wh[j][f]
__device__ float g_s1[NN];
__device__ float g_s2[NN];
__device__ __half g_F1h[NN];                // exp(s2 - max)            (<=1)
__device__ __half g_F2h[NN];                // exp(.2(s2 - max))        (<=1)
__device__ __half g_s2h[NN];                // s2 in fp16 (for branch)
__device__ __half g_E1h[NN];                // exp(s1 + max - B)        (<=1)
__device__ __half g_E2h[NN];                // exp(.2(s1 + max) - B)    (<=1)
__device__ __half g_ms1h[NN];               // -s1 in fp16
__device__ float g_maxS2;
__device__ float g_Opart[KSPLIT * NN * FF]; // 16 MB partial numerators
__device__ float g_den[KSPLIT * NN];        // partial denominators

// ---------------- packed f32x2 helpers (for K1) ------------------------------
__device__ __forceinline__ unsigned long long pk_dup(float x) {
    unsigned long long r;
    asm("mov.b64 %0, {%1, %1};" : "=l"(r) : "f"(x));
    return r;
}
__device__ __forceinline__ void ffma2(unsigned long long &d,
                                      unsigned long long a,
                                      unsigned long long b) {
    asm("fma.rn.f32x2 %0, %1, %2, %0;" : "+l"(d) : "l"(a), "l"(b));
}

// ---------------- mma / ldmatrix / cp.async helpers --------------------------
__device__ __forceinline__ uint32_t smem_u32(const void* p) {
    uint32_t a;
    asm("{ .reg .u64 t; cvta.to.shared.u64 t, %1; cvt.u32.u64 %0, t; }"
        : "=r"(a) : "l"(p));
    return a;
}
__device__ __forceinline__ void cp16(uint32_t dst, const void* src) {
    asm volatile("cp.async.cg.shared.global [%0], [%1], 16;"
                 :: "r"(dst), "l"(src) : "memory");
}
#define LDM4(d, addr)                                                          \
    asm volatile("ldmatrix.sync.aligned.m8n8.x4.shared.b16 {%0,%1,%2,%3}, [%4];" \
        : "=r"((d)[0]), "=r"((d)[1]), "=r"((d)[2]), "=r"((d)[3]) : "r"(addr))
#define LDM4T(d0, d1, d2, d3, addr)                                            \
    asm volatile("ldmatrix.sync.aligned.m8n8.x4.trans.shared.b16 {%0,%1,%2,%3}, [%4];" \
        : "=r"(d0), "=r"(d1), "=r"(d2), "=r"(d3) : "r"(addr))

__device__ __forceinline__ void mma16816(float* c, const uint32_t* a,
                                         uint32_t b0, uint32_t b1) {
    asm volatile(
        "mma.sync.aligned.m16n8k16.row.col.f32.f16.f16.f32 "
        "{%0,%1,%2,%3}, {%4,%5,%6,%7}, {%8,%9}, {%0,%1,%2,%3};"
        : "+f"(c[0]), "+f"(c[1]), "+f"(c[2]), "+f"(c[3])
        : "r"(a[0]), "r"(a[1]), "r"(a[2]), "r"(a[3]), "r"(b0), "r"(b1));
}

// one half2 pair of attention weights from packed fp16 factors
__device__ __forceinline__ uint32_t wpair(uint32_t f1, uint32_t f2, uint32_t s2,
                                          uint32_t E1d, uint32_t E2d,
                                          uint32_t ms1d, int a0, int a1) {
    __half2 c1 = __hmul2(*(__half2*)&E1d, *(__half2*)&f1);
    __half2 c2 = __hmul2(*(__half2*)&E2d, *(__half2*)&f2);
    uint32_t mk;   // 0xFFFF per half-lane where s2 >= -s1
    asm("set.ge.u32.f16x2 %0, %1, %2;" : "=r"(mk) : "r"(s2), "r"(ms1d));
    uint32_t u1 = *(uint32_t*)&c1, u2 = *(uint32_t*)&c2;
    uint32_t am = (uint32_t)(a0 + (a1 << 16)) * 0xFFFFu;  // adj in {0,1}
    return ((u1 & mk) | (u2 & ~mk)) & am;
}

// ==================== K1: Wh = h @ W (fp16 out), fused s1/s2 =================
__global__ void __launch_bounds__(256, 1)
k_wh(const float* __restrict__ h, const float* __restrict__ W,
     const float* __restrict__ a) {
    __shared__ float As[64 * 32];
    __shared__ float Ws[32 * 256];
    const int tid = threadIdx.x;
    const int i0 = blockIdx.x * 64;
    const int ty = tid >> 5, tx = tid & 31;
    const int r0 = ty * 8, c0 = tx * 8;

    unsigned long long acc[8][4];
#pragma unroll
    for (int r = 0; r < 8; r++)
#pragma unroll
        for (int p = 0; p < 4; p++) acc[r][p] = 0ull;

    for (int ko = 0; ko < FF; ko += 32) {
        __syncthreads();
#pragma unroll
        for (int t = 0; t < 2; t++) {
            int idx = t * 256 + tid;
            int row = idx >> 3, c4 = idx & 7;
            float4 v = *(const float4*)&h[(size_t)(i0 + row) * FF + ko + c4 * 4];
            *(float4*)&As[row * 32 + c4 * 4] = v;
        }
#pragma unroll
        for (int t = 0; t < 8; t++) {
            int idx = t * 256 + tid;
            int row = idx >> 6, c4 = idx & 63;
            float4 v = *(const float4*)&W[(size_t)(ko + row) * FF + c4 * 4];
            *(float4*)&Ws[row * 256 + c4 * 4] = v;
        }
        __syncthreads();
        for (int kk = 0; kk < 32; kk += 4) {
            float4 pv[8];
#pragma unroll
            for (int r = 0; r < 8; r++)
                pv[r] = *(const float4*)&As[(r0 + r) * 32 + kk];
#pragma unroll
            for (int k4 = 0; k4 < 4; k4++) {
                ulonglong2 wa = *(const ulonglong2*)&Ws[(kk + k4) * 256 + c0];
                ulonglong2 wb = *(const ulonglong2*)&Ws[(kk + k4) * 256 + c0 + 4];
#pragma unroll
                for (int r = 0; r < 8; r++) {
                    float p = (k4 == 0) ? pv[r].x : (k4 == 1) ? pv[r].y
                             : (k4 == 2) ? pv[r].z : pv[r].w;
                    unsigned long long pd = pk_dup(p);
                    ffma2(acc[r][0], pd, wa.x);
                    ffma2(acc[r][1], pd, wa.y);
                    ffma2(acc[r][2], pd, wb.x);
                    ffma2(acc[r][3], pd, wb.y);
                }
            }
        }
    }
    float mat[8][8];
#pragma unroll
    for (int r = 0; r < 8; r++)
#pragma unroll
        for (int p = 0; p < 4; p++) {
            float2 f = *(float2*)&acc[r][p];
            mat[r][2 * p] = f.x; mat[r][2 * p + 1] = f.y;
        }
    float a1c[8], a2c[8];
#pragma unroll
    for (int c = 0; c < 8; c++) { a1c[c] = a[c0 + c]; a2c[c] = a[FF + c0 + c]; }
#pragma unroll
    for (int r = 0; r < 8; r++) {
        float p1 = 0.f, p2 = 0.f;
#pragma unroll
        for (int c = 0; c < 8; c++) { p1 += mat[r][c] * a1c[c]; p2 += mat[r][c] * a2c[c]; }
#pragma unroll
        for (int off = 16; off > 0; off >>= 1) {
            p1 += __shfl_down_sync(0xffffffffu, p1, off);
            p2 += __shfl_down_sync(0xffffffffu, p2, off);
        }
        if (tx == 0) { g_s1[i0 + r0 + r] = p1; g_s2[i0 + r0 + r] = p2; }
    }
#pragma unroll
    for (int r = 0; r < 8; r++) {
        __half2 q0 = __floats2half2_rn(mat[r][0], mat[r][1]);
        __half2 q1 = __floats2half2_rn(mat[r][2], mat[r][3]);
        __half2 q2 = __floats2half2_rn(mat[r][4], mat[r][5]);
        __half2 q3 = __floats2half2_rn(mat[r][6], mat[r][7]);
        uint4 u = make_uint4(*(uint32_t*)&q0, *(uint32_t*)&q1,
                             *(uint32_t*)&q2, *(uint32_t*)&q3);
        *(uint4*)&g_Wh[(size_t)(i0 + r0 + r) * FF + c0] = u;
    }
}

// ==================== K2: maxS2 = max(s2) ====================================
__global__ void k_max() {
    __shared__ float sm[256];
    int tid = threadIdx.x;
    float v = -1e30f;
    for (int i = tid; i < NN; i += 256) v = fmaxf(v, g_s2[i]);
    sm[tid] = v;
    __syncthreads();
    for (int s = 128; s > 0; s >>= 1) {
        if (tid < s) sm[tid] = fmaxf(sm[tid], sm[tid + s]);
        __syncthreads();
    }
    if (tid == 0) g_maxS2 = sm[0];
}

// ==================== K3: factorized-exp precompute (fp16 factors) ===========
// B_i = leakyrelu(s1_i + maxS2) >= max_j e_ij.  All stored factors are <= 1.
__global__ void k_factors() {
    int i = blockIdx.x * blockDim.x + threadIdx.x;
    if (i >= NN) return;
    float s1 = g_s1[i], s2 = g_s2[i], m = g_maxS2;
    float x = s1 + m;
    float B = x > 0.f ? x : LRA * x;
    g_F1h[i] = __float2half(__expf(s2 - m));
    g_F2h[i] = __float2half(__expf(LRA * (s2 - m)));
    g_s2h[i] = __float2half(s2);
    g_E1h[i] = __float2half(__expf(s1 + m - B));
    g_E2h[i] = __float2half(__expf(LRA * (s1 + m) - B));
    g_ms1h[i] = __float2half(-s1);
}

// ==================== K4: fp16 mma.sync fused masked-softmax @ Wh ============
// grid (KSPLIT, 128), 256 thr (8 warps, warp tile 32x64), 2 CTAs/SM.
// 2 tiles per barrier epoch: P x4, B x4, one cp group + one sync per 2 tiles.
// Single factor/adj register set X, reused 3x per epoch.
__global__ void __launch_bounds__(256, 2)
k_attn(const int* __restrict__ adj) {
    extern __shared__ char smem[];
    const uint32_t PsB = smem_u32(smem);
    const uint32_t BsB = PsB + 4 * PBUF_BYTES;

    const int tid = threadIdx.x;
    const int lane = tid & 31, wid = tid >> 5;
    const int split = blockIdx.x;
    const int i0 = blockIdx.y * MB;
    const int jb = split * JSPAN;
    const int prow = tid >> 2;          // 0..63: this thread's P row
    const int jq = (tid & 3) * 8;       // 8 j's within tile
    const int wm = (wid & 1) * 32;      // warp M offset
    const int wn = (wid >> 1) * 64;     // warp N offset
    const bool doDen = (wid < 2);       // warps 0,1 accumulate denominators

    // per-row fp16 factors (duplicated into both half2 lanes)
    const uint32_t E1d = __half_as_ushort(g_E1h[i0 + prow]) * 0x10001u;
    const uint32_t E2d = __half_as_ushort(g_E2h[i0 + prow]) * 0x10001u;
    const uint32_t ms1d = __half_as_ushort(g_ms1h[i0 + prow]) * 0x10001u;

    const uint32_t Aoff = (uint32_t)(wm + (lane & 15)) * (PSTRIDE * 2) +
                          (uint32_t)(lane >> 4) * 16;
    const uint32_t Boff = (uint32_t)(lane & 15) * (BSTRIDE * 2) +
                          (uint32_t)(wn + (lane >> 4) * 8) * 2;
    const uint32_t Poff = (uint32_t)prow * (PSTRIDE * 2) + (uint32_t)jq * 2;

    float acc[2][8][4];
#pragma unroll
    for (int mf = 0; mf < 2; mf++)
#pragma unroll
        for (int nf = 0; nf < 8; nf++)
#pragma unroll
            for (int q = 0; q < 4; q++) acc[mf][nf][q] = 0.f;
    float dacc[2][4] = {{0.f, 0.f, 0.f, 0.f}, {0.f, 0.f, 0.f, 0.f}};

    // single register prefetch set X (factors + adj for one future tile)
    uint4 f1q, f2q, s2q;
    int4 av0, av1;

    auto ldnext = [&](int tt) {
        const int j0 = jb + tt * KT + jq;
        f1q = *(const uint4*)&g_F1h[j0];
        f2q = *(const uint4*)&g_F2h[j0];
        s2q = *(const uint4*)&g_s2h[j0];
        const size_t base = (size_t)(i0 + prow) * NN + j0;
        av0 = *(const int4*)&adj[base];
        av1 = *(const int4*)&adj[base + 4];
    };
    auto buildP = [&](uint32_t pb) {   // consumes the prefetched registers
        uint32_t hp0 = wpair(f1q.x, f2q.x, s2q.x, E1d, E2d, ms1d, av0.x, av0.y);
        uint32_t hp1 = wpair(f1q.y, f2q.y, s2q.y, E1d, E2d, ms1d, av0.z, av0.w);
        uint32_t hp2 = wpair(f1q.z, f2q.z, s2q.z, E1d, E2d, ms1d, av1.x, av1.y);
        uint32_t hp3 = wpair(f1q.w, f2q.w, s2q.w, E1d, E2d, ms1d, av1.z, av1.w);
        asm volatile("st.shared.v4.b32 [%0], {%1,%2,%3,%4};"
                     :: "r"(pb + Poff), "r"(hp0), "r"(hp1), "r"(hp2), "r"(hp3)
                     : "memory");
    };
    auto cpB = [&](int tt, uint32_t bb) {
        const int j0 = jb + tt * KT;
#pragma unroll
        for (int k = 0; k < 4; k++) {
            int c = tid + k * 256;
            int jr = c >> 5, fo = (c & 31) * 8;
            cp16(bb + (uint32_t)jr * (BSTRIDE * 2) + (uint32_t)fo * 2,
                 &g_Wh[(size_t)(j0 + jr) * FF + fo]);
        }
    };
    auto mmaT = [&](uint32_t Pb, uint32_t Bb) {
#pragma unroll
        for (int kf = 0; kf < 2; kf++) {
            uint32_t afr0[4], afr1[4];
            LDM4(afr0, Pb + Aoff + kf * 32);
            LDM4(afr1, Pb + Aoff + 16 * (PSTRIDE * 2) + kf * 32);
#pragma unroll
            for (int nfp = 0; nfp < 4; nfp++) {
                uint32_t b0, b1, b2, b3;
                LDM4T(b0, b1, b2, b3, Bb + Boff + nfp * 32 + kf * 16 * (BSTRIDE * 2));
                mma16816(acc[0][2 * nfp],     afr0, b0, b1);
                mma16816(acc[1][2 * nfp],     afr1, b0, b1);
                mma16816(acc[0][2 * nfp + 1], afr0, b2, b3);
                mma16816(acc[1][2 * nfp + 1], afr1, b2, b3);
            }
            if (doDen) {    // row sums via ones-column MMA (exactly consistent)
                mma16816(dacc[0], afr0, ONESF, ONESF);
                mma16816(dacc[1], afr1, ONESF, ONESF);
            }
        }
    };

    // ---- prologue: build P0,P1; land B0,B1; X <- tile 2 ----
    ldnext(0); buildP(PsB + 0 * PBUF_BYTES);
    cpB(0, BsB + 0 * BBUF_BYTES);
    cpB(1, BsB + 1 * BBUF_BYTES);
    asm volatile("cp.async.commit_group;" ::: "memory");
    ldnext(1); buildP(PsB + 1 * PBUF_BYTES);
    ldnext(2);
    asm volatile("cp.async.wait_group 0;" ::: "memory");
    __syncthreads();

#pragma unroll 1
    for (int t = 0; t < NTILE; t += 2) {
        // ---- tile t ----
        mmaT(PsB + (uint32_t)(t & 3) * PBUF_BYTES,
             BsB + (uint32_t)(t & 3) * BBUF_BYTES);
        // B copies for next epoch: latency spans MMA(t+1) + buildP
        if (t + 2 < NTILE) {
            cpB(t + 2, BsB + (uint32_t)((t + 2) & 3) * BBUF_BYTES);
            cpB(t + 3, BsB + (uint32_t)((t + 3) & 3) * BBUF_BYTES);
        }
        asm volatile("cp.async.commit_group;" ::: "memory");
        if (t + 2 < NTILE) buildP(PsB + (uint32_t)((t + 2) & 3) * PBUF_BYTES);
        if (t + 3 < NTILE) ldnext(t + 3);     // hides under MMA(t+1)
        // ---- tile t+1 ----
        mmaT(PsB + (uint32_t)((t + 1) & 3) * PBUF_BYTES,
             BsB + (uint32_t)((t + 1) & 3) * BBUF_BYTES);
        if (t + 3 < NTILE) buildP(PsB + (uint32_t)((t + 3) & 3) * PBUF_BYTES);
        if (t + 4 < NTILE) ldnext(t + 4);     // persists into next epoch
        asm volatile("cp.async.wait_group 0;" ::: "memory");
        __syncthreads();
    }

    // ---- denominators from tensor-core row sums ----
    const int gid = lane >> 2, tig = lane & 3;
    if (doDen && tig == 0) {
        g_den[split * NN + i0 + wm + gid]          = dacc[0][0];
        g_den[split * NN + i0 + wm + gid + 8]      = dacc[0][2];
        g_den[split * NN + i0 + wm + 16 + gid]     = dacc[1][0];
        g_den[split * NN + i0 + wm + 16 + gid + 8] = dacc[1][2];
    }

    // ---- partial O store ----
    float* Ob = g_Opart + (size_t)split * NN * FF;
#pragma unroll
    for (int mf = 0; mf < 2; mf++)
#pragma unroll
        for (int nf = 0; nf < 8; nf++) {
            int r = i0 + wm + mf * 16 + gid;
            int c = wn + nf * 8 + 2 * tig;
            *(float2*)&Ob[(size_t)r * FF + c] =
                make_float2(acc[mf][nf][0], acc[mf][nf][1]);
            *(float2*)&Ob[(size_t)(r + 8) * FF + c] =
                make_float2(acc[mf][nf][2], acc[mf][nf][3]);
        }
}

// ==================== K5: combine splits, divide, elu ========================
__global__ void k_final(float* __restrict__ out) {
    int idx = blockIdx.x * blockDim.x + threadIdx.x;   // float4 index
    int i = idx >> 6;                                   // row
    float den = g_den[i] + g_den[NN + i];
    float inv = 1.0f / den;
    const float4* O = (const float4*)g_Opart;
    const int STR = NN * FF / 4;
    float4 a = O[idx], b = O[idx + STR];
    float4 r;
    r.x = (a.x + b.x) * inv;
    r.y = (a.y + b.y) * inv;
    r.z = (a.z + b.z) * inv;
    r.w = (a.w + b.w) * inv;
    r.x = r.x > 0.f ? r.x : expm1f(r.x);
    r.y = r.y > 0.f ? r.y : expm1f(r.y);
    r.z = r.z > 0.f ? r.z : expm1f(r.z);
    r.w = r.w > 0.f ? r.w : expm1f(r.w);
    ((float4*)out)[idx] = r;
}

// ==================== launch =================================================
extern "C" void kernel_launch(void* const* d_in, const int* in_sizes, int n_in,
                              void* d_out, int out_size) {
    const float* h   = (const float*)d_in[0];
    const int*   adj = (const int*)d_in[1];
    const float* W   = (const float*)d_in[2];
    const float* a   = (const float*)d_in[3];
    float* out = (float*)d_out;

    k_wh<<<NN / 64, 256>>>(h, W, a);
    k_max<<<1, 256>>>();
    k_factors<<<NN / 256, 256>>>();

    const int smem_attn = 4 * PBUF_BYTES + 4 * BBUF_BYTES;   // 88064
    cudaFuncSetAttribute(k_attn, cudaFuncAttributeMaxDynamicSharedMemorySize,
                         smem_attn);
    k_attn<<<dim3(KSPLIT, NN / MB), 256, smem_attn>>>(adj);

    k_final<<<(NN * FF / 4) / 256, 256>>>(out);
}

// round 13
// speedup vs baseline: 1.5703x; 1.0477x over previous
#include <cuda_runtime.h>
#include <cuda_fp16.h>
#include <math.h>
#include <stdint.h>

#define NN 8192
#define FF 256
#define LRA 0.2f
#define KSPLIT 2
#define MB 64                   // i-rows per block in k_attn
#define KT 32                   // j (K-dim) per tile
#define JSPAN (NN / KSPLIT)     // 4096
#define NTILE (JSPAN / KT)      // 128

#define PSTRIDE 40                       // halves per P row (80 B)
#define PBUF_BYTES (64 * PSTRIDE * 2)    // 5120
#define BSTRIDE 264                      // halves per B row (528 B)
#define BBUF_BYTES (32 * BSTRIDE * 2)    // 16896
#define ONESF 0x3C003C00u                // half2(1,1)

// ---------------- scratch (device globals: no allocs allowed) ----------------
__device__ __half g_Wh[NN * FF];            // 4 MB, fp16 Wh[j][f]
__device__ __half g_h16[NN * FF];           // fp16 h
__device__ __half g_W16[FF * FF];           // fp16 W
__device__ float g_s1[NN];
__device__ float g_s2[NN];
__device__ __half g_F1h[NN];                // exp(s2 - max)            (<=1)
__device__ __half g_F2h[NN];                // exp(.2(s2 - max))        (<=1)
__device__ __half g_s2h[NN];                // s2 in fp16 (for branch)
__device__ __half g_E1h[NN];                // exp(s1 + max - B)        (<=1)
__device__ __half g_E2h[NN];                // exp(.2(s1 + max) - B)    (<=1)
__device__ __half g_ms1h[NN];               // -s1 in fp16
__device__ unsigned g_maxS2u = 0u;          // order-preserving-encoded max(s2)
__device__ float g_Opart[KSPLIT * NN * FF]; // 16 MB partial numerators
__device__ float g_den[2 * KSPLIT * NN];    // partial denominators (kf x split)

// ---------------- mma / ldmatrix / cp.async helpers --------------------------
__device__ __forceinline__ uint32_t smem_u32(const void* p) {
    uint32_t a;
    asm("{ .reg .u64 t; cvta.to.shared.u64 t, %1; cvt.u32.u64 %0, t; }"
        : "=r"(a) : "l"(p));
    return a;
}
__device__ __forceinline__ void cp16(uint32_t dst, const void* src) {
    asm volatile("cp.async.cg.shared.global [%0], [%1], 16;"
                 :: "r"(dst), "l"(src) : "memory");
}
#define LDM4(d, addr)                                                          \
    asm volatile("ldmatrix.sync.aligned.m8n8.x4.shared.b16 {%0,%1,%2,%3}, [%4];" \
        : "=r"((d)[0]), "=r"((d)[1]), "=r"((d)[2]), "=r"((d)[3]) : "r"(addr))
#define LDM4T(d0, d1, d2, d3, addr)                                            \
    asm volatile("ldmatrix.sync.aligned.m8n8.x4.trans.shared.b16 {%0,%1,%2,%3}, [%4];" \
        : "=r"(d0), "=r"(d1), "=r"(d2), "=r"(d3) : "r"(addr))

__device__ __forceinline__ void mma16816(float* c, const uint32_t* a,
                                         uint32_t b0, uint32_t b1) {
    asm volatile(
        "mma.sync.aligned.m16n8k16.row.col.f32.f16.f16.f32 "
        "{%0,%1,%2,%3}, {%4,%5,%6,%7}, {%8,%9}, {%0,%1,%2,%3};"
        : "+f"(c[0]), "+f"(c[1]), "+f"(c[2]), "+f"(c[3])
        : "r"(a[0]), "r"(a[1]), "r"(a[2]), "r"(a[3]), "r"(b0), "r"(b1));
}

// one half2 pair of attention weights from packed fp16 factors
__device__ __forceinline__ uint32_t wpair(uint32_t f1, uint32_t f2, uint32_t s2,
                                          uint32_t E1d, uint32_t E2d,
                                          uint32_t ms1d, int a0, int a1) {
    __half2 c1 = __hmul2(*(__half2*)&E1d, *(__half2*)&f1);
    __half2 c2 = __hmul2(*(__half2*)&E2d, *(__half2*)&f2);
    uint32_t mk;   // 0xFFFF per half-lane where s2 >= -s1
    asm("set.ge.u32.f16x2 %0, %1, %2;" : "=r"(mk) : "r"(s2), "r"(ms1d));
    uint32_t u1 = *(uint32_t*)&c1, u2 = *(uint32_t*)&c2;
    uint32_t am = (uint32_t)(a0 + (a1 << 16)) * 0xFFFFu;  // adj in {0,1}
    return ((u1 & mk) | (u2 & ~mk)) & am;
}

// order-preserving float<->uint encoding for atomicMax
__device__ __forceinline__ unsigned encf(float f) {
    unsigned u = __float_as_uint(f);
    return (u & 0x80000000u) ? ~u : (u | 0x80000000u);
}
__device__ __forceinline__ float decf(unsigned u) {
    return (u & 0x80000000u) ? __uint_as_float(u ^ 0x80000000u)
                             : __uint_as_float(~u);
}

// ==================== K0: convert h, W to fp16 ===============================
__global__ void k_h2f(const float* __restrict__ h, const float* __restrict__ W) {
    int idx4 = blockIdx.x * blockDim.x + threadIdx.x;    // float4 index
    const int H4 = NN * FF / 4;
    if (idx4 < H4) {
        float4 v = ((const float4*)h)[idx4];
        __half2 a = __floats2half2_rn(v.x, v.y);
        __half2 b = __floats2half2_rn(v.z, v.w);
        *(uint2*)&g_h16[idx4 * 4] = make_uint2(*(uint32_t*)&a, *(uint32_t*)&b);
    } else {
        int w4 = idx4 - H4;
        if (w4 < FF * FF / 4) {
            float4 v = ((const float4*)W)[w4];
            __half2 a = __floats2half2_rn(v.x, v.y);
            __half2 b = __floats2half2_rn(v.z, v.w);
            *(uint2*)&g_W16[w4 * 4] = make_uint2(*(uint32_t*)&a, *(uint32_t*)&b);
        }
    }
}

// ==================== K1: Wh = h16 @ W16 via HMMA ============================
// grid 128, 256 thr, CTA 64 rows x 256 cols, warp tile 32x64, K=256 (8 tiles).
__global__ void __launch_bounds__(256, 1)
k_whmma() {
    extern __shared__ char smem[];
    const uint32_t AsB = smem_u32(smem);                  // 2 x 5120
    const uint32_t BsB = AsB + 2 * PBUF_BYTES;            // 2 x 16896

    const int tid = threadIdx.x;
    const int lane = tid & 31, wid = tid >> 5;
    const int i0 = blockIdx.x * 64;
    const int wm = (wid & 1) * 32;
    const int wn = (wid >> 1) * 64;

    const uint32_t Aoff = (uint32_t)(wm + (lane & 15)) * (PSTRIDE * 2) +
                          (uint32_t)(lane >> 4) * 16;
    const uint32_t Boff = (uint32_t)(lane & 15) * (BSTRIDE * 2) +
                          (uint32_t)(wn + (lane >> 4) * 8) * 2;

    float acc[2][8][4];
#pragma unroll
    for (int mf = 0; mf < 2; mf++)
#pragma unroll
        for (int nf = 0; nf < 8; nf++)
#pragma unroll
            for (int q = 0; q < 4; q++) acc[mf][nf][q] = 0.f;

    auto cpA = [&](int kt, uint32_t ab) {   // 64 rows x 32 halves
        int row = tid >> 2, c16 = tid & 3;
        cp16(ab + (uint32_t)row * (PSTRIDE * 2) + (uint32_t)c16 * 16,
             &g_h16[(size_t)(i0 + row) * FF + kt * 32 + c16 * 8]);
    };
    auto cpBW = [&](int kt, uint32_t bb) {  // 32 k-rows x 256 cols
#pragma unroll
        for (int k = 0; k < 4; k++) {
            int c = tid + k * 256;
            int jr = c >> 5, fo = (c & 31) * 8;
            cp16(bb + (uint32_t)jr * (BSTRIDE * 2) + (uint32_t)fo * 2,
                 &g_W16[(size_t)(kt * 32 + jr) * FF + fo]);
        }
    };

    cpA(0, AsB); cpBW(0, BsB);
    asm volatile("cp.async.commit_group;" ::: "memory");
    cpA(1, AsB + PBUF_BYTES); cpBW(1, BsB + BBUF_BYTES);
    asm volatile("cp.async.commit_group;" ::: "memory");

#pragma unroll 1
    for (int kt = 0; kt < 8; kt++) {
        if (kt < 7)
            asm volatile("cp.async.wait_group 1;" ::: "memory");
        else
            asm volatile("cp.async.wait_group 0;" ::: "memory");
        __syncthreads();
        const uint32_t Ab = AsB + (uint32_t)(kt & 1) * PBUF_BYTES;
        const uint32_t Bb = BsB + (uint32_t)(kt & 1) * BBUF_BYTES;
#pragma unroll
        for (int kf = 0; kf < 2; kf++) {
            uint32_t afr0[4], afr1[4];
            LDM4(afr0, Ab + Aoff + kf * 32);
            LDM4(afr1, Ab + Aoff + 16 * (PSTRIDE * 2) + kf * 32);
#pragma unroll
            for (int nfp = 0; nfp < 4; nfp++) {
                uint32_t b0, b1, b2, b3;
                LDM4T(b0, b1, b2, b3, Bb + Boff + nfp * 32 + kf * 16 * (BSTRIDE * 2));
                mma16816(acc[0][2 * nfp],     afr0, b0, b1);
                mma16816(acc[1][2 * nfp],     afr1, b0, b1);
                mma16816(acc[0][2 * nfp + 1], afr0, b2, b3);
                mma16816(acc[1][2 * nfp + 1], afr1, b2, b3);
            }
        }
        __syncthreads();
        if (kt + 2 < 8) {
            cpA(kt + 2, Ab);
            cpBW(kt + 2, Bb);
        }
        asm volatile("cp.async.commit_group;" ::: "memory");
    }

    // store fp16 Wh (same fragment->coords mapping as k_attn Opart store)
    const int gid = lane >> 2, tig = lane & 3;
#pragma unroll
    for (int mf = 0; mf < 2; mf++)
#pragma unroll
        for (int nf = 0; nf < 8; nf++) {
            int r = i0 + wm + mf * 16 + gid;
            int c = wn + nf * 8 + 2 * tig;
            __half2 lo = __floats2half2_rn(acc[mf][nf][0], acc[mf][nf][1]);
            __half2 hi = __floats2half2_rn(acc[mf][nf][2], acc[mf][nf][3]);
            *(uint32_t*)&g_Wh[(size_t)r * FF + c] = *(uint32_t*)&lo;
            *(uint32_t*)&g_Wh[(size_t)(r + 8) * FF + c] = *(uint32_t*)&hi;
        }
}

// ==================== K2: s1,s2 = Wh.a1, Wh.a2 + atomic max(s2) ==============
// warp per row: grid 1024 x 256 thr
__global__ void k_s(const float* __restrict__ a) {
    const int tid = threadIdx.x;
    const int lane = tid & 31;
    const int row = blockIdx.x * 8 + (tid >> 5);
    uint4 w = *(const uint4*)&g_Wh[(size_t)row * FF + lane * 8];
    float4 a1a = *(const float4*)&a[lane * 8];
    float4 a1b = *(const float4*)&a[lane * 8 + 4];
    float4 a2a = *(const float4*)&a[FF + lane * 8];
    float4 a2b = *(const float4*)&a[FF + lane * 8 + 4];
    float2 v0 = __half22float2(*(__half2*)&w.x);
    float2 v1 = __half22float2(*(__half2*)&w.y);
    float2 v2 = __half22float2(*(__half2*)&w.z);
    float2 v3 = __half22float2(*(__half2*)&w.w);
    float p1 = v0.x * a1a.x + v0.y * a1a.y + v1.x * a1a.z + v1.y * a1a.w +
               v2.x * a1b.x + v2.y * a1b.y + v3.x * a1b.z + v3.y * a1b.w;
    float p2 = v0.x * a2a.x + v0.y * a2a.y + v1.x * a2a.z + v1.y * a2a.w +
               v2.x * a2b.x + v2.y * a2b.y + v3.x * a2b.z + v3.y * a2b.w;
#pragma unroll
    for (int off = 16; off > 0; off >>= 1) {
        p1 += __shfl_down_sync(0xffffffffu, p1, off);
        p2 += __shfl_down_sync(0xffffffffu, p2, off);
    }
    if (lane == 0) {
        g_s1[row] = p1;
        g_s2[row] = p2;
        atomicMax(&g_maxS2u, encf(p2));
    }
}

// ==================== K3: factorized-exp precompute (fp16 factors) ===========
__global__ void k_factors() {
    int i = blockIdx.x * blockDim.x + threadIdx.x;
    if (i >= NN) return;
    float s1 = g_s1[i], s2 = g_s2[i], m = decf(g_maxS2u);
    float x = s1 + m;
    float B = x > 0.f ? x : LRA * x;
    g_F1h[i] = __float2half(__expf(s2 - m));
    g_F2h[i] = __float2half(__expf(LRA * (s2 - m)));
    g_s2h[i] = __float2half(s2);
    g_E1h[i] = __float2half(__expf(s1 + m - B));
    g_E2h[i] = __float2half(__expf(LRA * (s1 + m) - B));
    g_ms1h[i] = __float2half(-s1);
}

// ==================== K4: fp16 mma.sync fused masked-softmax @ Wh ============
// grid (KSPLIT, 128), 256 thr (8 warps, warp tile 32x64), 2 CTAs/SM.
// 2 tiles per barrier epoch; cpBs hoisted to epoch start; den spread warps 0-3.
__global__ void __launch_bounds__(256, 2)
k_attn(const int* __restrict__ adj) {
    extern __shared__ char smem[];
    const uint32_t PsB = smem_u32(smem);
    const uint32_t BsB = PsB + 4 * PBUF_BYTES;

    const int tid = threadIdx.x;
    const int lane = tid & 31, wid = tid >> 5;
    const int split = blockIdx.x;
    const int i0 = blockIdx.y * MB;
    const int jb = split * JSPAN;
    const int prow = tid >> 2;          // 0..63: this thread's P row
    const int jq = (tid & 3) * 8;       // 8 j's within tile
    const int wm = (wid & 1) * 32;      // warp M offset
    const int wn = (wid >> 1) * 64;     // warp N offset

    // per-row fp16 factors (duplicated into both half2 lanes)
    const uint32_t E1d = __half_as_ushort(g_E1h[i0 + prow]) * 0x10001u;
    const uint32_t E2d = __half_as_ushort(g_E2h[i0 + prow]) * 0x10001u;
    const uint32_t ms1d = __half_as_ushort(g_ms1h[i0 + prow]) * 0x10001u;

    const uint32_t Aoff = (uint32_t)(wm + (lane & 15)) * (PSTRIDE * 2) +
                          (uint32_t)(lane >> 4) * 16;
    const uint32_t Boff = (uint32_t)(lane & 15) * (BSTRIDE * 2) +
                          (uint32_t)(wn + (lane >> 4) * 8) * 2;
    const uint32_t Poff = (uint32_t)prow * (PSTRIDE * 2) + (uint32_t)jq * 2;

    float acc[2][8][4];
#pragma unroll
    for (int mf = 0; mf < 2; mf++)
#pragma unroll
        for (int nf = 0; nf < 8; nf++)
#pragma unroll
            for (int q = 0; q < 4; q++) acc[mf][nf][q] = 0.f;
    float dacc[2][4] = {{0.f, 0.f, 0.f, 0.f}, {0.f, 0.f, 0.f, 0.f}};

    // single register prefetch set X (factors + adj for one future tile)
    uint4 f1q, f2q, s2q;
    int4 av0, av1;

    auto ldnext = [&](int tt) {
        const int j0 = jb + tt * KT + jq;
        f1q = *(const uint4*)&g_F1h[j0];
        f2q = *(const uint4*)&g_F2h[j0];
        s2q = *(const uint4*)&g_s2h[j0];
        const size_t base = (size_t)(i0 + prow) * NN + j0;
        av0 = *(const int4*)&adj[base];
        av1 = *(const int4*)&adj[base + 4];
    };
    auto buildP = [&](uint32_t pb) {   // consumes the prefetched registers
        uint32_t hp0 = wpair(f1q.x, f2q.x, s2q.x, E1d, E2d, ms1d, av0.x, av0.y);
        uint32_t hp1 = wpair(f1q.y, f2q.y, s2q.y, E1d, E2d, ms1d, av0.z, av0.w);
        uint32_t hp2 = wpair(f1q.z, f2q.z, s2q.z, E1d, E2d, ms1d, av1.x, av1.y);
        uint32_t hp3 = wpair(f1q.w, f2q.w, s2q.w, E1d, E2d, ms1d, av1.z, av1.w);
        asm volatile("st.shared.v4.b32 [%0], {%1,%2,%3,%4};"
                     :: "r"(pb + Poff), "r"(hp0), "r"(hp1), "r"(hp2), "r"(hp3)
                     : "memory");
    };
    auto cpB = [&](int tt, uint32_t bb) {
        const int j0 = jb + tt * KT;
#pragma unroll
        for (int k = 0; k < 4; k++) {
            int c = tid + k * 256;
            int jr = c >> 5, fo = (c & 31) * 8;
            cp16(bb + (uint32_t)jr * (BSTRIDE * 2) + (uint32_t)fo * 2,
                 &g_Wh[(size_t)(j0 + jr) * FF + fo]);
        }
    };
    auto mmaT = [&](uint32_t Pb, uint32_t Bb) {
#pragma unroll
        for (int kf = 0; kf < 2; kf++) {
            uint32_t afr0[4], afr1[4];
            LDM4(afr0, Pb + Aoff + kf * 32);
            LDM4(afr1, Pb + Aoff + 16 * (PSTRIDE * 2) + kf * 32);
#pragma unroll
            for (int nfp = 0; nfp < 4; nfp++) {
                uint32_t b0, b1, b2, b3;
                LDM4T(b0, b1, b2, b3, Bb + Boff + nfp * 32 + kf * 16 * (BSTRIDE * 2));
                mma16816(acc[0][2 * nfp],     afr0, b0, b1);
                mma16816(acc[1][2 * nfp],     afr1, b0, b1);
                mma16816(acc[0][2 * nfp + 1], afr0, b2, b3);
                mma16816(acc[1][2 * nfp + 1], afr1, b2, b3);
            }
            // den spread: warps 0,1 handle kf=0; warps 2,3 handle kf=1
            if (wid < 4 && (wid >> 1) == kf) {
                mma16816(dacc[0], afr0, ONESF, ONESF);
                mma16816(dacc[1], afr1, ONESF, ONESF);
            }
        }
    };

    // ---- prologue: build P0,P1; land B0,B1; X <- tile 2 ----
    ldnext(0); buildP(PsB + 0 * PBUF_BYTES);
    cpB(0, BsB + 0 * BBUF_BYTES);
    cpB(1, BsB + 1 * BBUF_BYTES);
    asm volatile("cp.async.commit_group;" ::: "memory");
    ldnext(1); buildP(PsB + 1 * PBUF_BYTES);
    ldnext(2);
    asm volatile("cp.async.wait_group 0;" ::: "memory");
    __syncthreads();

#pragma unroll 1
    for (int t = 0; t < NTILE; t += 2) {
        // B copies for next epoch first: max cp.async cover
        if (t + 2 < NTILE) {
            cpB(t + 2, BsB + (uint32_t)((t + 2) & 3) * BBUF_BYTES);
            cpB(t + 3, BsB + (uint32_t)((t + 3) & 3) * BBUF_BYTES);
        }
        asm volatile("cp.async.commit_group;" ::: "memory");
        // ---- tile t ----
        mmaT(PsB + (uint32_t)(t & 3) * PBUF_BYTES,
             BsB + (uint32_t)(t & 3) * BBUF_BYTES);
        if (t + 2 < NTILE) buildP(PsB + (uint32_t)((t + 2) & 3) * PBUF_BYTES);
        if (t + 3 < NTILE) ldnext(t + 3);     // hides under MMA(t+1)
        // ---- tile t+1 ----
        mmaT(PsB + (uint32_t)((t + 1) & 3) * PBUF_BYTES,
             BsB + (uint32_t)((t + 1) & 3) * BBUF_BYTES);
        if (t + 3 < NTILE) buildP(PsB + (uint32_t)((t + 3) & 3) * PBUF_BYTES);
        if (t + 4 < NTILE) ldnext(t + 4);     // persists into next epoch
        asm volatile("cp.async.wait_group 0;" ::: "memory");
        __syncthreads();
    }

    // ---- denominators from tensor-core row sums (4 partial slots) ----
    const int gid = lane >> 2, tig = lane & 3;
    if (wid < 4 && tig == 0) {
        int part = wid >> 1;
        float* dp = g_den + ((size_t)(part * KSPLIT + split)) * NN + i0 + wm;
        dp[gid]          = dacc[0][0];
        dp[gid + 8]      = dacc[0][2];
        dp[16 + gid]     = dacc[1][0];
        dp[16 + gid + 8] = dacc[1][2];
    }

    // ---- partial O store ----
    float* Ob = g_Opart + (size_t)split * NN * FF;
#pragma unroll
    for (int mf = 0; mf < 2; mf++)
#pragma unroll
        for (int nf = 0; nf < 8; nf++) {
            int r = i0 + wm + mf * 16 + gid;
            int c = wn + nf * 8 + 2 * tig;
            *(float2*)&Ob[(size_t)r * FF + c] =
                make_float2(acc[mf][nf][0], acc[mf][nf][1]);
            *(float2*)&Ob[(size_t)(r + 8) * FF + c] =
                make_float2(acc[mf][nf][2], acc[mf][nf][3]);
        }
}

// ==================== K5: combine splits, divide, elu ========================
__global__ void k_final(float* __restrict__ out) {
    int idx = blockIdx.x * blockDim.x + threadIdx.x;   // float4 index
    if (idx == 0) g_maxS2u = 0u;                       // reset for next launch
    int i = idx >> 6;                                   // row
    float den = (g_den[i] + g_den[NN + i]) +
                (g_den[2 * NN + i] + g_den[3 * NN + i]);
    float inv = 1.0f / den;
    const float4* O = (const float4*)g_Opart;
    const int STR = NN * FF / 4;
    float4 a = O[idx], b = O[idx + STR];
    float4 r;
    r.x = (a.x + b.x) * inv;
    r.y = (a.y + b.y) * inv;
    r.z = (a.z + b.z) * inv;
    r.w = (a.w + b.w) * inv;
    r.x = r.x > 0.f ? r.x : expm1f(r.x);
    r.y = r.y > 0.f ? r.y : expm1f(r.y);
    r.z = r.z > 0.f ? r.z : expm1f(r.z);
    r.w = r.w > 0.f ? r.w : expm1f(r.w);
    ((float4*)out)[idx] = r;
}

// ==================== launch =================================================
extern "C" void kernel_launch(void* const* d_in, const int* in_sizes, int n_in,
                              void* d_out, int out_size) {
    const float* h   = (const float*)d_in[0];
    const int*   adj = (const int*)d_in[1];
    const float* W   = (const float*)d_in[2];
    const float* a   = (const float*)d_in[3];
    float* out = (float*)d_out;

    const int cvt4 = (NN * FF + FF * FF) / 4;
    k_h2f<<<(cvt4 + 255) / 256, 256>>>(h, W);

    const int smem_wh = 2 * PBUF_BYTES + 2 * BBUF_BYTES;     // 44032
    k_whmma<<<NN / 64, 256, smem_wh>>>();

    k_s<<<NN / 8, 256>>>(a);
    k_factors<<<NN / 256, 256>>>();

    const int smem_attn = 4 * PBUF_BYTES + 4 * BBUF_BYTES;   // 88064
    cudaFuncSetAttribute(k_attn, cudaFuncAttributeMaxDynamicSharedMemorySize,
                         smem_attn);
    k_attn<<<dim3(KSPLIT, NN / MB), 256, smem_attn>>>(adj);

    k_final<<<(NN * FF / 4) / 256, 256>>>(out);
}

// round 14
// speedup vs baseline: 1.6311x; 1.0387x over previous
#include <cuda_runtime.h>
#include <cuda_fp16.h>
#include <math.h>
#include <stdint.h>

#define NN 8192
#define FF 256
#define LRA 0.2f
#define KSPLIT 2
#define MB 64                   // i-rows per block in k_attn
#define KT 32                   // j (K-dim) per tile
#define JSPAN (NN / KSPLIT)     // 4096
#define NTILE (JSPAN / KT)      // 128

#define PSTRIDE 40                       // halves per P row (80 B)
#define PBUF_BYTES (64 * PSTRIDE * 2)    // 5120
#define BSTRIDE 264                      // halves per B row (528 B)
#define BBUF_BYTES (32 * BSTRIDE * 2)    // 16896
#define ONESF 0x3C003C00u                // half2(1,1)

// ---------------- scratch (device globals: no allocs allowed) ----------------
__device__ __half g_Wh[NN * FF];            // 4 MB, fp16 Wh[j][f]
__device__ __half g_W16[FF * FF];           // fp16 W
__device__ float g_s1[NN];
__device__ float g_s2[NN];
__device__ __half g_F1h[NN];                // exp(s2 - max)            (<=1)
__device__ __half g_F2h[NN];                // exp(.2(s2 - max))        (<=1)
__device__ __half g_s2h[NN];                // s2 in fp16 (for branch)
__device__ __half g_E1h[NN];                // exp(s1 + max - B)        (<=1)
__device__ __half g_E2h[NN];                // exp(.2(s1 + max) - B)    (<=1)
__device__ __half g_ms1h[NN];               // -s1 in fp16
__device__ unsigned g_maxS2u = 0u;          // order-preserving-encoded max(s2)
__device__ float g_Opart[KSPLIT * NN * FF]; // 16 MB partial numerators
__device__ float g_den[2 * KSPLIT * NN];    // partial denominators (kf x split)

// ---------------- mma / ldmatrix / cp.async helpers --------------------------
__device__ __forceinline__ uint32_t smem_u32(const void* p) {
    uint32_t a;
    asm("{ .reg .u64 t; cvta.to.shared.u64 t, %1; cvt.u32.u64 %0, t; }"
        : "=r"(a) : "l"(p));
    return a;
}
__device__ __forceinline__ void cp16(uint32_t dst, const void* src) {
    asm volatile("cp.async.cg.shared.global [%0], [%1], 16;"
                 :: "r"(dst), "l"(src) : "memory");
}
#define LDM4(d, addr)                                                          \
    asm volatile("ldmatrix.sync.aligned.m8n8.x4.shared.b16 {%0,%1,%2,%3}, [%4];" \
        : "=r"((d)[0]), "=r"((d)[1]), "=r"((d)[2]), "=r"((d)[3]) : "r"(addr))
#define LDM4T(d0, d1, d2, d3, addr)                                            \
    asm volatile("ldmatrix.sync.aligned.m8n8.x4.trans.shared.b16 {%0,%1,%2,%3}, [%4];" \
        : "=r"(d0), "=r"(d1), "=r"(d2), "=r"(d3) : "r"(addr))

__device__ __forceinline__ void mma16816(float* c, const uint32_t* a,
                                         uint32_t b0, uint32_t b1) {
    asm volatile(
        "mma.sync.aligned.m16n8k16.row.col.f32.f16.f16.f32 "
        "{%0,%1,%2,%3}, {%4,%5,%6,%7}, {%8,%9}, {%0,%1,%2,%3};"
        : "+f"(c[0]), "+f"(c[1]), "+f"(c[2]), "+f"(c[3])
        : "r"(a[0]), "r"(a[1]), "r"(a[2]), "r"(a[3]), "r"(b0), "r"(b1));
}

// one half2 pair of attention weights from packed fp16 factors
__device__ __forceinline__ uint32_t wpair(uint32_t f1, uint32_t f2, uint32_t s2,
                                          uint32_t E1d, uint32_t E2d,
                                          uint32_t ms1d, int a0, int a1) {
    __half2 c1 = __hmul2(*(__half2*)&E1d, *(__half2*)&f1);
    __half2 c2 = __hmul2(*(__half2*)&E2d, *(__half2*)&f2);
    uint32_t mk;   // 0xFFFF per half-lane where s2 >= -s1
    asm("set.ge.u32.f16x2 %0, %1, %2;" : "=r"(mk) : "r"(s2), "r"(ms1d));
    uint32_t u1 = *(uint32_t*)&c1, u2 = *(uint32_t*)&c2;
    uint32_t am = (uint32_t)(a0 + (a1 << 16)) * 0xFFFFu;  // adj in {0,1}
    return ((u1 & mk) | (u2 & ~mk)) & am;
}

// order-preserving float<->uint encoding for atomicMax
__device__ __forceinline__ unsigned encf(float f) {
    unsigned u = __float_as_uint(f);
    return (u & 0x80000000u) ? ~u : (u | 0x80000000u);
}
__device__ __forceinline__ float decf(unsigned u) {
    return (u & 0x80000000u) ? __uint_as_float(u ^ 0x80000000u)
                             : __uint_as_float(~u);
}

// ==================== K0: convert W to fp16 ==================================
__global__ void k_w16(const float* __restrict__ W) {
    int i4 = blockIdx.x * blockDim.x + threadIdx.x;      // float4 index
    float4 v = ((const float4*)W)[i4];
    __half2 a = __floats2half2_rn(v.x, v.y);
    __half2 b = __floats2half2_rn(v.z, v.w);
    *(uint2*)&g_W16[i4 * 4] = make_uint2(*(uint32_t*)&a, *(uint32_t*)&b);
}

// ==================== K1: Wh = h @ W16 via HMMA; fused s1/s2 + max ===========
// grid 128, 256 thr, CTA 64 rows x 256 cols, warp tile 32x64.
// h converted in-kernel into a resident 8-tile smem A region (40 KB).
__global__ void __launch_bounds__(256, 1)
k_whmma(const float* __restrict__ h, const float* __restrict__ a) {
    extern __shared__ char smem[];
    const uint32_t AsB = smem_u32(smem);                  // 8 x 5120 = 40960
    const uint32_t BsB = AsB + 8 * PBUF_BYTES;            // 2 x 16896
    __shared__ float sa[2 * FF];                          // a1 | a2
    __shared__ float sP1[64], sP2[64];

    const int tid = threadIdx.x;
    const int lane = tid & 31, wid = tid >> 5;
    const int i0 = blockIdx.x * 64;
    const int wm = (wid & 1) * 32;
    const int wn = (wid >> 1) * 64;

    const uint32_t Aoff = (uint32_t)(wm + (lane & 15)) * (PSTRIDE * 2) +
                          (uint32_t)(lane >> 4) * 16;
    const uint32_t Boff = (uint32_t)(lane & 15) * (BSTRIDE * 2) +
                          (uint32_t)(wn + (lane >> 4) * 8) * 2;

    // ---- stage a into smem; zero dot buffers ----
    if (tid < 128) *(float4*)&sa[tid * 4] = *(const float4*)&a[tid * 4];
    if (tid < 64) { sP1[tid] = 0.f; sP2[tid] = 0.f; }

    // ---- convert this CTA's 64 h rows into resident A region ----
#pragma unroll
    for (int seg = 0; seg < 4; seg++) {
        int idx = seg * 256 + tid;            // 0..1023
        int row = idx >> 4, s16 = idx & 15;
        int col0 = s16 * 16;
        int kt = col0 >> 5, off = col0 & 31;
        const float* hp = &h[(size_t)(i0 + row) * FF + col0];
        float4 v0 = *(const float4*)&hp[0];
        float4 v1 = *(const float4*)&hp[4];
        float4 v2 = *(const float4*)&hp[8];
        float4 v3 = *(const float4*)&hp[12];
        __half2 q0 = __floats2half2_rn(v0.x, v0.y), q1 = __floats2half2_rn(v0.z, v0.w);
        __half2 q2 = __floats2half2_rn(v1.x, v1.y), q3 = __floats2half2_rn(v1.z, v1.w);
        __half2 q4 = __floats2half2_rn(v2.x, v2.y), q5 = __floats2half2_rn(v2.z, v2.w);
        __half2 q6 = __floats2half2_rn(v3.x, v3.y), q7 = __floats2half2_rn(v3.z, v3.w);
        uint32_t ad = AsB + (uint32_t)kt * PBUF_BYTES +
                      (uint32_t)row * (PSTRIDE * 2) + (uint32_t)off * 2;
        asm volatile("st.shared.v4.b32 [%0], {%1,%2,%3,%4};"
                     :: "r"(ad), "r"(*(uint32_t*)&q0), "r"(*(uint32_t*)&q1),
                        "r"(*(uint32_t*)&q2), "r"(*(uint32_t*)&q3) : "memory");
        asm volatile("st.shared.v4.b32 [%0], {%1,%2,%3,%4};"
                     :: "r"(ad + 16), "r"(*(uint32_t*)&q4), "r"(*(uint32_t*)&q5),
                        "r"(*(uint32_t*)&q6), "r"(*(uint32_t*)&q7) : "memory");
    }

    auto cpBW = [&](int kt, uint32_t bb) {  // 32 k-rows x 256 cols of W16
#pragma unroll
        for (int k = 0; k < 4; k++) {
            int c = tid + k * 256;
            int jr = c >> 5, fo = (c & 31) * 8;
            cp16(bb + (uint32_t)jr * (BSTRIDE * 2) + (uint32_t)fo * 2,
                 &g_W16[(size_t)(kt * 32 + jr) * FF + fo]);
        }
    };

    float acc[2][8][4];
#pragma unroll
    for (int mf = 0; mf < 2; mf++)
#pragma unroll
        for (int nf = 0; nf < 8; nf++)
#pragma unroll
            for (int q = 0; q < 4; q++) acc[mf][nf][q] = 0.f;

    cpBW(0, BsB);
    asm volatile("cp.async.commit_group;" ::: "memory");
    cpBW(1, BsB + BBUF_BYTES);
    asm volatile("cp.async.commit_group;" ::: "memory");

#pragma unroll 1
    for (int kt = 0; kt < 8; kt++) {
        if (kt < 7)
            asm volatile("cp.async.wait_group 1;" ::: "memory");
        else
            asm volatile("cp.async.wait_group 0;" ::: "memory");
        __syncthreads();
        const uint32_t Ab = AsB + (uint32_t)kt * PBUF_BYTES;
        const uint32_t Bb = BsB + (uint32_t)(kt & 1) * BBUF_BYTES;
#pragma unroll
        for (int kf = 0; kf < 2; kf++) {
            uint32_t afr0[4], afr1[4];
            LDM4(afr0, Ab + Aoff + kf * 32);
            LDM4(afr1, Ab + Aoff + 16 * (PSTRIDE * 2) + kf * 32);
#pragma unroll
            for (int nfp = 0; nfp < 4; nfp++) {
                uint32_t b0, b1, b2, b3;
                LDM4T(b0, b1, b2, b3, Bb + Boff + nfp * 32 + kf * 16 * (BSTRIDE * 2));
                mma16816(acc[0][2 * nfp],     afr0, b0, b1);
                mma16816(acc[1][2 * nfp],     afr1, b0, b1);
                mma16816(acc[0][2 * nfp + 1], afr0, b2, b3);
                mma16816(acc[1][2 * nfp + 1], afr1, b2, b3);
            }
        }
        __syncthreads();
        if (kt + 2 < 8) cpBW(kt + 2, Bb);
        asm volatile("cp.async.commit_group;" ::: "memory");
    }

    // ---- store fp16 Wh + per-thread partial dots with a1/a2 ----
    const int gid = lane >> 2, tig = lane & 3;
    float p1lo[2] = {0.f, 0.f}, p1hi[2] = {0.f, 0.f};
    float p2lo[2] = {0.f, 0.f}, p2hi[2] = {0.f, 0.f};
#pragma unroll
    for (int mf = 0; mf < 2; mf++)
#pragma unroll
        for (int nf = 0; nf < 8; nf++) {
            int r = i0 + wm + mf * 16 + gid;
            int c = wn + nf * 8 + 2 * tig;
            __half2 lo = __floats2half2_rn(acc[mf][nf][0], acc[mf][nf][1]);
            __half2 hi = __floats2half2_rn(acc[mf][nf][2], acc[mf][nf][3]);
            *(uint32_t*)&g_Wh[(size_t)r * FF + c] = *(uint32_t*)&lo;
            *(uint32_t*)&g_Wh[(size_t)(r + 8) * FF + c] = *(uint32_t*)&hi;
            float a1x = sa[c], a1y = sa[c + 1];
            float a2x = sa[FF + c], a2y = sa[FF + c + 1];
            p1lo[mf] += acc[mf][nf][0] * a1x + acc[mf][nf][1] * a1y;
            p1hi[mf] += acc[mf][nf][2] * a1x + acc[mf][nf][3] * a1y;
            p2lo[mf] += acc[mf][nf][0] * a2x + acc[mf][nf][1] * a2y;
            p2hi[mf] += acc[mf][nf][2] * a2x + acc[mf][nf][3] * a2y;
        }
    // reduce across tig (4 lanes share a row-set), accumulate across wn warps
#pragma unroll
    for (int mf = 0; mf < 2; mf++) {
#pragma unroll
        for (int off = 2; off > 0; off >>= 1) {
            p1lo[mf] += __shfl_down_sync(0xffffffffu, p1lo[mf], off, 4);
            p1hi[mf] += __shfl_down_sync(0xffffffffu, p1hi[mf], off, 4);
            p2lo[mf] += __shfl_down_sync(0xffffffffu, p2lo[mf], off, 4);
            p2hi[mf] += __shfl_down_sync(0xffffffffu, p2hi[mf], off, 4);
        }
        if (tig == 0) {
            int rl = wm + mf * 16 + gid;
            atomicAdd(&sP1[rl], p1lo[mf]);
            atomicAdd(&sP1[rl + 8], p1hi[mf]);
            atomicAdd(&sP2[rl], p2lo[mf]);
            atomicAdd(&sP2[rl + 8], p2hi[mf]);
        }
    }
    __syncthreads();
    if (tid < 64) {
        float s1 = sP1[tid], s2 = sP2[tid];
        g_s1[i0 + tid] = s1;
        g_s2[i0 + tid] = s2;
        // block max of s2 -> one atomicMax per warp-half
        float m = s2;
#pragma unroll
        for (int off = 16; off > 0; off >>= 1)
            m = fmaxf(m, __shfl_down_sync(0xffffffffu, m, off));
        if (lane == 0) atomicMax(&g_maxS2u, encf(m));
    }
}

// ==================== K3: factorized-exp precompute (fp16 factors) ===========
__global__ void k_factors() {
    int i = blockIdx.x * blockDim.x + threadIdx.x;
    if (i >= NN) return;
    float s1 = g_s1[i], s2 = g_s2[i], m = decf(g_maxS2u);
    float x = s1 + m;
    float B = x > 0.f ? x : LRA * x;
    g_F1h[i] = __float2half(__expf(s2 - m));
    g_F2h[i] = __float2half(__expf(LRA * (s2 - m)));
    g_s2h[i] = __float2half(s2);
    g_E1h[i] = __float2half(__expf(s1 + m - B));
    g_E2h[i] = __float2half(__expf(LRA * (s1 + m) - B));
    g_ms1h[i] = __float2half(-s1);
}

// ==================== K4: fp16 mma.sync fused masked-softmax @ Wh ============
// grid (KSPLIT, 128), 256 thr (8 warps, warp tile 32x64), 2 CTAs/SM.
// 2 tiles per barrier epoch; cpBs hoisted to epoch start; den spread warps 0-3.
__global__ void __launch_bounds__(256, 2)
k_attn(const int* __restrict__ adj) {
    extern __shared__ char smem[];
    const uint32_t PsB = smem_u32(smem);
    const uint32_t BsB = PsB + 4 * PBUF_BYTES;

    const int tid = threadIdx.x;
    const int lane = tid & 31, wid = tid >> 5;
    const int split = blockIdx.x;
    const int i0 = blockIdx.y * MB;
    const int jb = split * JSPAN;
    const int prow = tid >> 2;          // 0..63: this thread's P row
    const int jq = (tid & 3) * 8;       // 8 j's within tile
    const int wm = (wid & 1) * 32;      // warp M offset
    const int wn = (wid >> 1) * 64;     // warp N offset

    // per-row fp16 factors (duplicated into both half2 lanes)
    const uint32_t E1d = __half_as_ushort(g_E1h[i0 + prow]) * 0x10001u;
    const uint32_t E2d = __half_as_ushort(g_E2h[i0 + prow]) * 0x10001u;
    const uint32_t ms1d = __half_as_ushort(g_ms1h[i0 + prow]) * 0x10001u;

    const uint32_t Aoff = (uint32_t)(wm + (lane & 15)) * (PSTRIDE * 2) +
                          (uint32_t)(lane >> 4) * 16;
    const uint32_t Boff = (uint32_t)(lane & 15) * (BSTRIDE * 2) +
                          (uint32_t)(wn + (lane >> 4) * 8) * 2;
    const uint32_t Poff = (uint32_t)prow * (PSTRIDE * 2) + (uint32_t)jq * 2;

    float acc[2][8][4];
#pragma unroll
    for (int mf = 0; mf < 2; mf++)
#pragma unroll
        for (int nf = 0; nf < 8; nf++)
#pragma unroll
            for (int q = 0; q < 4; q++) acc[mf][nf][q] = 0.f;
    float dacc[2][4] = {{0.f, 0.f, 0.f, 0.f}, {0.f, 0.f, 0.f, 0.f}};

    // single register prefetch set X (factors + adj for one future tile)
    uint4 f1q, f2q, s2q;
    int4 av0, av1;

    auto ldnext = [&](int tt) {
        const int j0 = jb + tt * KT + jq;
        f1q = *(const uint4*)&g_F1h[j0];
        f2q = *(const uint4*)&g_F2h[j0];
        s2q = *(const uint4*)&g_s2h[j0];
        const size_t base = (size_t)(i0 + prow) * NN + j0;
        av0 = *(const int4*)&adj[base];
        av1 = *(const int4*)&adj[base + 4];
    };
    auto buildP = [&](uint32_t pb) {   // consumes the prefetched registers
        uint32_t hp0 = wpair(f1q.x, f2q.x, s2q.x, E1d, E2d, ms1d, av0.x, av0.y);
        uint32_t hp1 = wpair(f1q.y, f2q.y, s2q.y, E1d, E2d, ms1d, av0.z, av0.w);
        uint32_t hp2 = wpair(f1q.z, f2q.z, s2q.z, E1d, E2d, ms1d, av1.x, av1.y);
        uint32_t hp3 = wpair(f1q.w, f2q.w, s2q.w, E1d, E2d, ms1d, av1.z, av1.w);
        asm volatile("st.shared.v4.b32 [%0], {%1,%2,%3,%4};"
                     :: "r"(pb + Poff), "r"(hp0), "r"(hp1), "r"(hp2), "r"(hp3)
                     : "memory");
    };
    auto cpB = [&](int tt, uint32_t bb) {
        const int j0 = jb + tt * KT;
#pragma unroll
        for (int k = 0; k < 4; k++) {
            int c = tid + k * 256;
            int jr = c >> 5, fo = (c & 31) * 8;
            cp16(bb + (uint32_t)jr * (BSTRIDE * 2) + (uint32_t)fo * 2,
                 &g_Wh[(size_t)(j0 + jr) * FF + fo]);
        }
    };
    auto mmaT = [&](uint32_t Pb, uint32_t Bb) {
#pragma unroll
        for (int kf = 0; kf < 2; kf++) {
            uint32_t afr0[4], afr1[4];
            LDM4(afr0, Pb + Aoff + kf * 32);
            LDM4(afr1, Pb + Aoff + 16 * (PSTRIDE * 2) + kf * 32);
#pragma unroll
            for (int nfp = 0; nfp < 4; nfp++) {
                uint32_t b0, b1, b2, b3;
                LDM4T(b0, b1, b2, b3, Bb + Boff + nfp * 32 + kf * 16 * (BSTRIDE * 2));
                mma16816(acc[0][2 * nfp],     afr0, b0, b1);
                mma16816(acc[1][2 * nfp],     afr1, b0, b1);
                mma16816(acc[0][2 * nfp + 1], afr0, b2, b3);
                mma16816(acc[1][2 * nfp + 1], afr1, b2, b3);
            }
            // den spread: warps 0,1 handle kf=0; warps 2,3 handle kf=1
            if (wid < 4 && (wid >> 1) == kf) {
                mma16816(dacc[0], afr0, ONESF, ONESF);
                mma16816(dacc[1], afr1, ONESF, ONESF);
            }
        }
    };

    // ---- prologue: build P0,P1; land B0,B1; X <- tile 2 ----
    ldnext(0); buildP(PsB + 0 * PBUF_BYTES);
    cpB(0, BsB + 0 * BBUF_BYTES);
    cpB(1, BsB + 1 * BBUF_BYTES);
    asm volatile("cp.async.commit_group;" ::: "memory");
    ldnext(1); buildP(PsB + 1 * PBUF_BYTES);
    ldnext(2);
    asm volatile("cp.async.wait_group 0;" ::: "memory");
    __syncthreads();

#pragma unroll 1
    for (int t = 0; t < NTILE; t += 2) {
        // B copies for next epoch first: max cp.async cover
        if (t + 2 < NTILE) {
            cpB(t + 2, BsB + (uint32_t)((t + 2) & 3) * BBUF_BYTES);
            cpB(t + 3, BsB + (uint32_t)((t + 3) & 3) * BBUF_BYTES);
        }
        asm volatile("cp.async.commit_group;" ::: "memory");
        // ---- tile t ----
        mmaT(PsB + (uint32_t)(t & 3) * PBUF_BYTES,
             BsB + (uint32_t)(t & 3) * BBUF_BYTES);
        if (t + 2 < NTILE) buildP(PsB + (uint32_t)((t + 2) & 3) * PBUF_BYTES);
        if (t + 3 < NTILE) ldnext(t + 3);     // hides under MMA(t+1)
        // ---- tile t+1 ----
        mmaT(PsB + (uint32_t)((t + 1) & 3) * PBUF_BYTES,
             BsB + (uint32_t)((t + 1) & 3) * BBUF_BYTES);
        if (t + 3 < NTILE) buildP(PsB + (uint32_t)((t + 3) & 3) * PBUF_BYTES);
        if (t + 4 < NTILE) ldnext(t + 4);     // persists into next epoch
        asm volatile("cp.async.wait_group 0;" ::: "memory");
        __syncthreads();
    }

    // ---- denominators from tensor-core row sums (4 partial slots) ----
    const int gid = lane >> 2, tig = lane & 3;
    if (wid < 4 && tig == 0) {
        int part = wid >> 1;
        float* dp = g_den + ((size_t)(part * KSPLIT + split)) * NN + i0 + wm;
        dp[gid]          = dacc[0][0];
        dp[gid + 8]      = dacc[0][2];
        dp[16 + gid]     = dacc[1][0];
        dp[16 + gid + 8] = dacc[1][2];
    }

    // ---- partial O store ----
    float* Ob = g_Opart + (size_t)split * NN * FF;
#pragma unroll
    for (int mf = 0; mf < 2; mf++)
#pragma unroll
        for (int nf = 0; nf < 8; nf++) {
            int r = i0 + wm + mf * 16 + gid;
            int c = wn + nf * 8 + 2 * tig;
            *(float2*)&Ob[(size_t)r * FF + c] =
                make_float2(acc[mf][nf][0], acc[mf][nf][1]);
            *(float2*)&Ob[(size_t)(r + 8) * FF + c] =
                make_float2(acc[mf][nf][2], acc[mf][nf][3]);
        }
}

// ==================== K5: combine splits, divide, elu ========================
__global__ void k_final(float* __restrict__ out) {
    int idx = blockIdx.x * blockDim.x + threadIdx.x;   // float4 index
    if (idx == 0) g_maxS2u = 0u;                       // reset for next launch
    int i = idx >> 6;                                   // row
    float den = (g_den[i] + g_den[NN + i]) +
                (g_den[2 * NN + i] + g_den[3 * NN + i]);
    float inv = 1.0f / den;
    const float4* O = (const float4*)g_Opart;
    const int STR = NN * FF / 4;
    float4 a = O[idx], b = O[idx + STR];
    float4 r;
    r.x = (a.x + b.x) * inv;
    r.y = (a.y + b.y) * inv;
    r.z = (a.z + b.z) * inv;
    r.w = (a.w + b.w) * inv;
    r.x = r.x > 0.f ? r.x : expm1f(r.x);
    r.y = r.y > 0.f ? r.y : expm1f(r.y);
    r.z = r.z > 0.f ? r.z : expm1f(r.z);
    r.w = r.w > 0.f ? r.w : expm1f(r.w);
    ((float4*)out)[idx] = r;
}

// ==================== launch =================================================
extern "C" void kernel_launch(void* const* d_in, const int* in_sizes, int n_in,
                              void* d_out, int out_size) {
    const float* h   = (const float*)d_in[0];
    const int*   adj = (const int*)d_in[1];
    const float* W   = (const float*)d_in[2];
    const float* a   = (const float*)d_in[3];
    float* out = (float*)d_out;

    k_w16<<<FF * FF / 4 / 256, 256>>>(W);

    const int smem_wh = 8 * PBUF_BYTES + 2 * BBUF_BYTES;     // 74752
    cudaFuncSetAttribute(k_whmma, cudaFuncAttributeMaxDynamicSharedMemorySize,
                         smem_wh);
    k_whmma<<<NN / 64, 256, smem_wh>>>(h, a);

    k_factors<<<NN / 256, 256>>>();

    const int smem_attn = 4 * PBUF_BYTES + 4 * BBUF_BYTES;   // 88064
    cudaFuncSetAttribute(k_attn, cudaFuncAttributeMaxDynamicSharedMemorySize,
                         smem_attn);
    k_attn<<<dim3(KSPLIT, NN / MB), 256, smem_attn>>>(adj);

    k_final<<<(NN * FF / 4) / 256, 256>>>(out);
}